// round 9
// baseline (speedup 1.0000x reference)
#include <cuda_runtime.h>
#include <cstdint>

// DynamicTopGate, two-kernel version (round 9).
//
// Round-8 confirmed: occupancy + register headroom for load batching was the
// real bottleneck (113 -> 61.5us). Now GEMM1 (~47us) is jointly bound by FFMA
// issue (32us floor) and W1-from-L1 traffic (31us at 2 rows/warp). This round:
// 4 rows/warp halves W1 L1 traffic (-> ~16us), leaving a clean FFMA bound,
// while scalar accumulators (64 regs) keep 16 warps/SM and LDG batching room.
// Epilogue: 64-thread blocks to cover all 148 SMs.

#define IN_DIM 2048
#define NE     16
#define BMAX   16384

__device__ float g_h[BMAX * NE];   // raw GEMM1 sums (pre-tanh), 1 MB scratch

// ---------------------------------------------------------------------------
// Kernel A: h_raw[b, e] = sum_i x[b, i] * W1[e, i]
// 4 rows per warp, scalar accumulators, warp-butterfly reduction.
// ---------------------------------------------------------------------------
__global__ void __launch_bounds__(128, 4)
gemm1_kernel(const float* __restrict__ x, const float* __restrict__ W1, int B)
{
    const int lane = threadIdx.x & 31;
    const int gw   = blockIdx.x * 4 + (threadIdx.x >> 5);
    const int row0 = gw * 4;
    if (row0 >= B) return;

    const float4* x0 = reinterpret_cast<const float4*>(x + (size_t)row0 * IN_DIM) + lane;
    const float4* wp = reinterpret_cast<const float4*>(W1) + lane;

    float acc[4][NE];
    #pragma unroll
    for (int r = 0; r < 4; ++r)
        #pragma unroll
        for (int e = 0; e < NE; ++e) acc[r][e] = 0.0f;

    // 16 chunks of 128 columns (32 lanes x float4). Unroll 2 so ptxas
    // front-batches 8 x-row LDG.128s per body while the body stays I$-small.
    #pragma unroll 2
    for (int c = 0; c < IN_DIM / 128; ++c) {
        float4 a[4];
        #pragma unroll
        for (int r = 0; r < 4; ++r)
            a[r] = __ldcs(x0 + r * (IN_DIM / 4) + c * 32);   // stream x
        #pragma unroll
        for (int e = 0; e < NE; ++e) {
            float4 w = __ldg(wp + e * (IN_DIM / 4) + c * 32);  // W1 L1-resident
            #pragma unroll
            for (int r = 0; r < 4; ++r) {
                acc[r][e] = fmaf(a[r].x, w.x, fmaf(a[r].y, w.y,
                            fmaf(a[r].z, w.z, fmaf(a[r].w, w.w, acc[r][e]))));
            }
        }
    }

    // Butterfly-reduce each accumulator across the warp.
    #pragma unroll
    for (int r = 0; r < 4; ++r)
        #pragma unroll
        for (int e = 0; e < NE; ++e) {
            #pragma unroll
            for (int off = 16; off > 0; off >>= 1)
                acc[r][e] += __shfl_xor_sync(0xffffffffu, acc[r][e], off);
        }

    // Lanes 0-3 write rows row0..row0+3 (4x float4 each).
    if (lane < 4) {
        float4* hp = reinterpret_cast<float4*>(g_h + (size_t)(row0 + lane) * NE);
        #pragma unroll
        for (int q = 0; q < 4; ++q)
            hp[q] = make_float4(acc[lane][4 * q + 0], acc[lane][4 * q + 1],
                                acc[lane][4 * q + 2], acc[lane][4 * q + 3]);
    }
}

// ---------------------------------------------------------------------------
// Kernel B: per-row epilogue. tanh -> W2 -> /0.7 -> argsort16 -> softmax ->
// dynamic-k -> outputs. One thread per row, 64-thread blocks (SM coverage).
// ---------------------------------------------------------------------------

// Descending compare-exchange, stable (index-ascending) tie-break,
// matching jnp.argsort(-logits).
#define CE(a, b) do {                                                \
    float va = v[a], vb = v[b]; int ia = id[a], ib = id[b];          \
    bool sw = (vb > va) || (vb == va && ib < ia);                    \
    v[a] = sw ? vb : va; v[b] = sw ? va : vb;                        \
    id[a] = sw ? ib : ia; id[b] = sw ? ia : ib;                      \
} while (0);

__global__ void __launch_bounds__(64)
epilogue_kernel(const float* __restrict__ W2, float* __restrict__ out, int B)
{
    const int row = blockIdx.x * blockDim.x + threadIdx.x;
    if (row >= B) return;

    float h[NE];
    const float4* hp = reinterpret_cast<const float4*>(g_h + (size_t)row * NE);
    #pragma unroll
    for (int q = 0; q < NE / 4; ++q) {
        float4 hv = hp[q];
        h[4 * q + 0] = tanhf(hv.x);
        h[4 * q + 1] = tanhf(hv.y);
        h[4 * q + 2] = tanhf(hv.z);
        h[4 * q + 3] = tanhf(hv.w);
    }

    // logits[f] = (sum_e h[e] * W2[f, e]) / 0.7
    float v[NE]; int id[NE];
    const float4* W2v = reinterpret_cast<const float4*>(W2);
    #pragma unroll
    for (int f = 0; f < NE; ++f) {
        float s = 0.0f;
        #pragma unroll
        for (int q = 0; q < NE / 4; ++q) {
            float4 w = __ldg(W2v + f * (NE / 4) + q);
            s = fmaf(h[4 * q + 0], w.x, s);
            s = fmaf(h[4 * q + 1], w.y, s);
            s = fmaf(h[4 * q + 2], w.z, s);
            s = fmaf(h[4 * q + 3], w.w, s);
        }
        v[f] = s / 0.7f;
        id[f] = f;
    }

    // Batcher odd-even mergesort, n=16, 63 comparators, descending.
    CE(0,1) CE(2,3) CE(4,5) CE(6,7) CE(8,9) CE(10,11) CE(12,13) CE(14,15)
    CE(0,2) CE(1,3) CE(4,6) CE(5,7) CE(8,10) CE(9,11) CE(12,14) CE(13,15)
    CE(1,2) CE(5,6) CE(9,10) CE(13,14)
    CE(0,4) CE(1,5) CE(2,6) CE(3,7) CE(8,12) CE(9,13) CE(10,14) CE(11,15)
    CE(2,4) CE(3,5) CE(10,12) CE(11,13)
    CE(1,2) CE(3,4) CE(5,6) CE(9,10) CE(11,12) CE(13,14)
    CE(0,8) CE(1,9) CE(2,10) CE(3,11) CE(4,12) CE(5,13) CE(6,14) CE(7,15)
    CE(4,8) CE(5,9) CE(6,10) CE(7,11)
    CE(2,4) CE(3,5) CE(6,8) CE(7,9) CE(10,12) CE(11,13)
    CE(1,2) CE(3,4) CE(5,6) CE(7,8) CE(9,10) CE(11,12) CE(13,14)

    // Softmax over sorted logits (max = v[0]).
    float m = v[0];
    float p[NE]; float ssum = 0.0f;
    #pragma unroll
    for (int e = 0; e < NE; ++e) { p[e] = expf(v[e] - m); ssum += p[e]; }
    float inv = 1.0f / ssum;
    #pragma unroll
    for (int e = 0; e < NE; ++e) p[e] *= inv;

    // k from cumulative probability.
    int k = NE;
    float cum = 0.0f;
    #pragma unroll
    for (int e = 0; e < NE; ++e) {
        cum += p[e];
        if (k == NE && cum >= 0.92f) k = e + 1;
    }
    float p1 = p[0], p2 = p[1], p3 = p[2];
    if (p1 >= 0.46f && (p1 - p2) >= 0.1f) k = 1;
    if (k > 2 && ((p1 + p2) >= 0.82f || p3 <= 0.12f || (p2 - p3) <= 0.03f)) k = 2;
    if (k < 1) k = 1;
    if (k > 3) k = 3;

    float* oidx  = out;
    float* osc   = out + (size_t)B * 8;
    float* omask = out + (size_t)B * 16;
    float* okv   = out + (size_t)B * 24;
    #pragma unroll
    for (int j = 0; j < 8; ++j) {
        float msk = (j < k) ? 1.0f : 0.0f;
        oidx[row * 8 + j]  = (float)id[j];
        osc[row * 8 + j]   = p[j] * msk;
        omask[row * 8 + j] = msk;
    }
    okv[row] = (float)k;
}

extern "C" void kernel_launch(void* const* d_in, const int* in_sizes, int n_in,
                              void* d_out, int out_size)
{
    const float* x  = (const float*)d_in[0];
    const float* W1 = (const float*)d_in[1];
    const float* W2 = (const float*)d_in[2];
    float* out = (float*)d_out;

    int B = in_sizes[0] / IN_DIM;                 // 16384

    // Kernel A: 4 warps/block, 4 rows/warp -> 16 rows/block.
    int blocksA = (B + 15) / 16;                  // 1024
    gemm1_kernel<<<blocksA, 128>>>(x, W1, B);

    // Kernel B: 1 thread/row, 64-thread blocks -> 256 blocks.
    int blocksB = (B + 63) / 64;
    epilogue_kernel<<<blocksB, 64>>>(W2, out, B);
}